// round 12
// baseline (speedup 1.0000x reference)
#include <cuda_runtime.h>
#include <cuda_bf16.h>

#define PROPOSALS_PER_IM 300
#define HUBER_T 3.0f
#define THREADS 512

__device__ __forceinline__ float huber1(float d) {
    float a = fabsf(d);
    return (a < HUBER_T) ? d * d : a;
}

// EXACT = true when grid*THREADS == B: no bounds predicate on the load path.
template <bool EXACT>
__global__ void __launch_bounds__(THREADS)
_RPN_71459665871443_kernel(const float* __restrict__ out8,
                           const float* __restrict__ gt,
                           const int* __restrict__ cp,
                           float* __restrict__ d_out,
                           int B, float inv_n) {
    const int b = blockIdx.x * blockDim.x + threadIdx.x;
    float s = 0.0f;
    if (EXACT || b < B) {
        // max idx = 65535*300+299 < 2^25; float offset idx*8+4 < 2^28 -> int32 safe
        int idx = cp[b] + PROPOSALS_PER_IM * b;
        // pred_box = row cols [4..8): byte offset idx*32+16, 16B-aligned float4
        float4 p = *reinterpret_cast<const float4*>(out8 + idx * 8 + 4);
        float4 g = *reinterpret_cast<const float4*>(gt + 4 * b);
        s = huber1(p.x - g.x) + huber1(p.y - g.y) +
            huber1(p.z - g.z) + huber1(p.w - g.w);
    }

    // warp reduction
    #pragma unroll
    for (int off = 16; off > 0; off >>= 1)
        s += __shfl_down_sync(0xFFFFFFFFu, s, off);

    // block funnel: throttles same-address RED traffic — measured essential
    // (2048 direct warp-level REDs regressed to 9.9us in R10)
    __shared__ float warp_sums[THREADS / 32];
    const int lane = threadIdx.x & 31;
    const int wid  = threadIdx.x >> 5;
    if (lane == 0) warp_sums[wid] = s;
    __syncthreads();
    if (wid == 0) {
        s = (lane < (THREADS / 32)) ? warp_sums[lane] : 0.0f;
        #pragma unroll
        for (int off = 8; off > 0; off >>= 1)
            s += __shfl_down_sync(0xFFFFFFFFu, s, off);
        if (lane == 0)
            atomicAdd(d_out, s * inv_n);   // one RED per CTA, retire immediately
    }
}

extern "C" void kernel_launch(void* const* d_in, const int* in_sizes, int n_in,
                              void* d_out, int out_size) {
    // Identify inputs by element count (order-proof):
    //   output: B*300*8 (largest), central_pos: B (smallest), gt_boxes: B*4
    int i_out = 0, i_cp = 0;
    for (int i = 1; i < n_in; i++) {
        if (in_sizes[i] > in_sizes[i_out]) i_out = i;
        if (in_sizes[i] < in_sizes[i_cp])  i_cp  = i;
    }
    int i_gt = 0;
    for (int i = 0; i < n_in; i++)
        if (i != i_out && i != i_cp) { i_gt = i; break; }

    const float* out8 = (const float*)d_in[i_out];
    const float* gt   = (const float*)d_in[i_gt];
    const int*   cp   = (const int*)d_in[i_cp];
    float* out = (float*)d_out;

    int B = in_sizes[i_cp];
    float inv_n = 1.0f / (4.0f * (float)B);

    // Graph memset node (async, capturable) — hidden behind kernel dispatch.
    cudaMemsetAsync(out, 0, sizeof(float));

    int blocks = (B + THREADS - 1) / THREADS;   // B=65536 -> 128 blocks of 512
    if (blocks * THREADS == B)
        _RPN_71459665871443_kernel<true><<<blocks, THREADS>>>(out8, gt, cp, out, B, inv_n);
    else
        _RPN_71459665871443_kernel<false><<<blocks, THREADS>>>(out8, gt, cp, out, B, inv_n);
}

// round 13
// speedup vs baseline: 1.2718x; 1.2718x over previous
#include <cuda_runtime.h>
#include <cuda_bf16.h>

#define PROPOSALS_PER_IM 300
#define HUBER_T 3.0f
#define THREADS 256

__device__ __forceinline__ float huber1(float d) {
    float a = fabsf(d);
    return (a < HUBER_T) ? d * d : a;
}

// EXACT = true when grid*THREADS == B: no bounds predicate on the load path.
template <bool EXACT>
__global__ void __launch_bounds__(THREADS)
_RPN_71459665871443_kernel(const float* __restrict__ out8,
                           const float* __restrict__ gt,
                           const int* __restrict__ cp,
                           float* __restrict__ d_out,
                           int B, float inv_n) {
    const int b = blockIdx.x * blockDim.x + threadIdx.x;
    float s = 0.0f;
    if (EXACT || b < B) {
        // max idx = 65535*300+299 < 2^25; float offset idx*8+4 < 2^28 -> int32 safe
        int idx = cp[b] + PROPOSALS_PER_IM * b;
        // pred_box = row cols [4..8): byte offset idx*32+16, 16B-aligned float4
        float4 p = *reinterpret_cast<const float4*>(out8 + idx * 8 + 4);
        float4 g = *reinterpret_cast<const float4*>(gt + 4 * b);
        s = huber1(p.x - g.x) + huber1(p.y - g.y) +
            huber1(p.z - g.z) + huber1(p.w - g.w);
    }

    // warp reduction
    #pragma unroll
    for (int off = 16; off > 0; off >>= 1)
        s += __shfl_down_sync(0xFFFFFFFFu, s, off);

    // block funnel: throttles same-address RED traffic 8x — measured essential
    // (2048 direct warp-level REDs regressed to 9.9us in R10)
    __shared__ float warp_sums[THREADS / 32];
    const int lane = threadIdx.x & 31;
    const int wid  = threadIdx.x >> 5;
    if (lane == 0) warp_sums[wid] = s;
    __syncthreads();
    if (wid == 0) {
        s = (lane < (THREADS / 32)) ? warp_sums[lane] : 0.0f;
        #pragma unroll
        for (int off = 4; off > 0; off >>= 1)
            s += __shfl_down_sync(0xFFFFFFFFu, s, off);
        if (lane == 0)
            atomicAdd(d_out, s * inv_n);   // one RED per CTA, retire immediately
    }
}

extern "C" void kernel_launch(void* const* d_in, const int* in_sizes, int n_in,
                              void* d_out, int out_size) {
    // Identify inputs by element count (order-proof):
    //   output: B*300*8 (largest), central_pos: B (smallest), gt_boxes: B*4
    int i_out = 0, i_cp = 0;
    for (int i = 1; i < n_in; i++) {
        if (in_sizes[i] > in_sizes[i_out]) i_out = i;
        if (in_sizes[i] < in_sizes[i_cp])  i_cp  = i;
    }
    int i_gt = 0;
    for (int i = 0; i < n_in; i++)
        if (i != i_out && i != i_cp) { i_gt = i; break; }

    const float* out8 = (const float*)d_in[i_out];
    const float* gt   = (const float*)d_in[i_gt];
    const int*   cp   = (const int*)d_in[i_cp];
    float* out = (float*)d_out;

    int B = in_sizes[i_cp];
    float inv_n = 1.0f / (4.0f * (float)B);

    // Graph memset node (async, capturable) — hidden behind kernel dispatch.
    cudaMemsetAsync(out, 0, sizeof(float));

    int blocks = (B + THREADS - 1) / THREADS;   // B=65536 -> 256 blocks of 256
    if (blocks * THREADS == B)
        _RPN_71459665871443_kernel<true><<<blocks, THREADS>>>(out8, gt, cp, out, B, inv_n);
    else
        _RPN_71459665871443_kernel<false><<<blocks, THREADS>>>(out8, gt, cp, out, B, inv_n);
}